// round 14
// baseline (speedup 1.0000x reference)
#include <cuda_runtime.h>
#include <cuda_fp16.h>
#include <cstdint>

#define TPB 256
#define NWARP (TPB / 32)
#define CHUNK 64                    // rows per warp-chunk
#define LOGIT_B (CHUNK * 7 * 4)     // 1792 bytes of logits
#define BUF_B 2048                  // + 256 bytes of int32 targets = 128 float4

// entropy constants c[r] = sum_j t_j * log(t_j)
#define C0 (-1.3658296f)
#define C1 (-1.4694533f)
#define C2 (-1.6721570f)
#define C3 (-1.9459101f)            // log(1/7)

#define LOG2E 1.4426950408889634f
#define LN2   0.6931471805599453f

__device__ double   g_accum;
__device__ unsigned g_count;

#define CP16(dst, src) \
    asm volatile("cp.async.cg.shared.global [%0], [%1], 16;" :: "r"(dst), "l"(src))
#define CP_COMMIT()  asm volatile("cp.async.commit_group;")
#define CP_WAIT1()   asm volatile("cp.async.wait_group 1;")

__device__ __forceinline__ float row_kl7(float x0, float x1, float x2, float x3,
                                         float x4, float x5, float x6, int tv)
{
    const int idx = ((unsigned)tv <= 2u) ? tv : 3;

    // paired f16 exp: 4 MUFU instead of 7 (y in [-8.5,8.5] -> f16-safe)
    const __half2 h01 = __floats2half2_rn(x0 * LOG2E, x1 * LOG2E);
    const __half2 h23 = __floats2half2_rn(x2 * LOG2E, x3 * LOG2E);
    const __half2 h45 = __floats2half2_rn(x4 * LOG2E, x5 * LOG2E);
    const __half2 h66 = __floats2half2_rn(x6 * LOG2E, 0.0f);
    const float2 e01 = __half22float2(h2exp2(h01));
    const float2 e23 = __half22float2(h2exp2(h23));
    const float2 e45 = __half22float2(h2exp2(h45));
    const float2 e66 = __half22float2(h2exp2(h66));
    const float se  = ((e01.x + e01.y) + (e23.x + e23.y)) + ((e45.x + e45.y) + e66.x);
    const float lse = __log2f(se) * LN2;

    const float s  = x0 + x1 + x2 + x3 + x4 + x5 + x6;
    const float d0 = fmaf(0.05f, s, fmaf(-0.03f, x1, fmaf(-0.02f, x2, 0.35f * (x3 + x5))));
    const float d1 = fmaf(0.05f, s, fmaf( 0.25f, x4, 0.40f * x6));
    const float d2 = fmaf(0.15f, s, fmaf(-0.05f, x0, fmaf(0.05f, x2,
                     fmaf(-0.13f, x3, fmaf(0.2f, x4, -0.12f * x5)))));
    const float d3 = s * 0.14285715f;

    const float d = (idx == 0) ? d0 : (idx == 1) ? d1 : (idx == 2) ? d2 : d3;
    const float c = (idx == 0) ? C0 : (idx == 1) ? C1 : (idx == 2) ? C2 : C3;
    return c + lse - d;
}

__global__ void __launch_bounds__(TPB, 7)
k_fused(const float* __restrict__ em, const int* __restrict__ tg,
        float* __restrict__ out, int n, int nchunks)
{
    // per-warp private double buffer: [1792B logits][256B targets] x2
    __shared__ __align__(16) char s_x[NWARP][2][BUF_B];
    __shared__ float s_part[NWARP];
    __shared__ bool  s_last;

    const int wid  = threadIdx.x >> 5;
    const int lane = threadIdx.x & 31;
    const int gw   = blockIdx.x * NWARP + wid;   // global warp id
    const int nw   = gridDim.x * NWARP;          // total warps

    const uint32_t sb = (uint32_t)__cvta_generic_to_shared(&s_x[wid][0][0]);

    float acc = 0.f;
    int c = gw, buf = 0;

    // ---- prologue: prefetch first chunk (128 float4 = 4 per lane, no tail) ----
    if (c < nchunks) {
        const char* srcL = (const char*)(em + (size_t)c * (CHUNK * 7));
        const char* srcT = (const char*)(tg + (size_t)c * CHUNK);
        CP16(sb + lane * 16,        srcL + lane * 16);
        CP16(sb + (lane + 32) * 16, srcL + (lane + 32) * 16);
        CP16(sb + (lane + 64) * 16, srcL + (lane + 64) * 16);
        const char* s4 = (lane < 16) ? (srcL + (96 + lane) * 16)
                                     : (srcT + (lane - 16) * 16);
        CP16(sb + (96 + lane) * 16, s4);
    }
    CP_COMMIT();

    // ---- warp-private pipelined loop: no block barriers ----
    for (; c < nchunks; c += nw) {
        const int cn = c + nw;
        if (cn < nchunks) {
            const uint32_t db = sb + (buf ^ 1) * BUF_B;
            const char* srcL = (const char*)(em + (size_t)cn * (CHUNK * 7));
            const char* srcT = (const char*)(tg + (size_t)cn * CHUNK);
            CP16(db + lane * 16,        srcL + lane * 16);
            CP16(db + (lane + 32) * 16, srcL + (lane + 32) * 16);
            CP16(db + (lane + 64) * 16, srcL + (lane + 64) * 16);
            const char* s4 = (lane < 16) ? (srcL + (96 + lane) * 16)
                                         : (srcT + (lane - 16) * 16);
            CP16(db + (96 + lane) * 16, s4);
        }
        CP_COMMIT();          // possibly-empty group keeps wait-count uniform
        CP_WAIT1();           // own copies for current buf done
        __syncwarp();         // ... and every other lane's too

        const char* base = &s_x[wid][buf][0];
        // rows 2*lane, 2*lane+1: 14 contiguous floats @ 56*lane -> 7x LDS.64, phase-conflict-free
        const float2* p  = (const float2*)(base + lane * 56);
        const int2    tv = ((const int2*)(base + LOGIT_B))[lane];

        float x[14];
        #pragma unroll
        for (int j = 0; j < 7; ++j) { const float2 v = p[j]; x[2*j] = v.x; x[2*j+1] = v.y; }

        acc += row_kl7(x[0], x[1], x[2], x[3], x[4], x[5], x[6],  tv.x);
        acc += row_kl7(x[7], x[8], x[9], x[10], x[11], x[12], x[13], tv.y);

        __syncwarp();         // all lanes consumed buf before it refills next iter
        buf ^= 1;
    }

    // ---- tail rows (none when n % 64 == 0): direct global, block 0 ----
    if (blockIdx.x == 0) {
        for (int row = nchunks * CHUNK + threadIdx.x; row < n; row += TPB) {
            const float* xr = em + (size_t)row * 7;
            acc += row_kl7(xr[0], xr[1], xr[2], xr[3], xr[4], xr[5], xr[6], tg[row]);
        }
    }

    // ---- block reduction ----
    #pragma unroll
    for (int o = 16; o > 0; o >>= 1)
        acc += __shfl_xor_sync(0xFFFFFFFFu, acc, o);
    if (lane == 0) s_part[wid] = acc;
    __syncthreads();

    if (threadIdx.x < 32) {
        float v = (lane < NWARP) ? s_part[lane] : 0.f;
        #pragma unroll
        for (int o = 4; o > 0; o >>= 1)
            v += __shfl_xor_sync(0xFFFFFFFFu, v, o);
        if (lane == 0)
            atomicAdd(&g_accum, (double)v);
    }

    // ---- last-block finalize (self-resetting for graph replay determinism) ----
    if (threadIdx.x == 0) {
        __threadfence();
        unsigned t = atomicAdd(&g_count, 1u);
        s_last = (t == gridDim.x - 1);
    }
    __syncthreads();
    if (s_last && threadIdx.x == 0) {
        out[0]  = (float)(g_accum / (double)n);
        g_accum = 0.0;
        g_count = 0u;
    }
}

extern "C" void kernel_launch(void* const* d_in, const int* in_sizes, int n_in,
                              void* d_out, int out_size)
{
    // metadata order: [0] fatigue_logits (unused), [1] emotion_logits, [2] fatigue_targets
    const float* em = (const float*)d_in[1];
    const int*   tg = (const int*)d_in[2];
    const int n = in_sizes[2];

    const int nchunks = n / CHUNK;
    int grid = 148 * 7;   // persistent, one wave (32.3 KB smem/block -> 7 blocks/SM)
    const int needed = (nchunks + NWARP - 1) / NWARP;
    if (needed >= 1 && grid > needed) grid = needed;
    if (grid < 1) grid = 1;

    k_fused<<<grid, TPB>>>(em, tg, (float*)d_out, n, nchunks);
}

// round 15
// speedup vs baseline: 1.2760x; 1.2760x over previous
#include <cuda_runtime.h>
#include <cuda_fp16.h>
#include <cstdint>

#define TPB 256
#define NWARP (TPB / 32)
#define CHUNK 64                   // rows per warp-chunk
#define V4 (CHUNK * 7 / 4)         // 112 float4 per chunk
#define BUF_F (CHUNK * 7)          // 448 floats per buffer
#define BUF_B (BUF_F * 4)          // 1792 bytes

// entropy constants c[r] = sum_j t_j * log(t_j)
#define C0 (-1.3658296f)
#define C1 (-1.4694533f)
#define C2 (-1.6721570f)
#define C3 (-1.9459101f)           // log(1/7)

#define LOG2E 1.4426950408889634f
#define LN2   0.6931471805599453f

__device__ double   g_accum;
__device__ unsigned g_count;

#define CP16(dst, src) \
    asm volatile("cp.async.cg.shared.global [%0], [%1], 16;" :: "r"(dst), "l"(src))
#define CP_COMMIT()  asm volatile("cp.async.commit_group;")
#define CP_WAIT1()   asm volatile("cp.async.wait_group 1;")

__device__ __forceinline__ float row_kl(const float* __restrict__ xr, int tv)
{
    const int idx = ((unsigned)tv <= 2u) ? tv : 3;
    const float x0 = xr[0], x1 = xr[1], x2 = xr[2], x3 = xr[3],
                x4 = xr[4], x5 = xr[5], x6 = xr[6];

    // paired f16 exp: 4 MUFU instead of 7 (y in [-8.5,8.5] -> f16-safe)
    const __half2 h01 = __floats2half2_rn(x0 * LOG2E, x1 * LOG2E);
    const __half2 h23 = __floats2half2_rn(x2 * LOG2E, x3 * LOG2E);
    const __half2 h45 = __floats2half2_rn(x4 * LOG2E, x5 * LOG2E);
    const __half2 h66 = __floats2half2_rn(x6 * LOG2E, 0.0f);
    const float2 e01 = __half22float2(h2exp2(h01));
    const float2 e23 = __half22float2(h2exp2(h23));
    const float2 e45 = __half22float2(h2exp2(h45));
    const float2 e66 = __half22float2(h2exp2(h66));
    const float se  = ((e01.x + e01.y) + (e23.x + e23.y)) + ((e45.x + e45.y) + e66.x);
    const float lse = __log2f(se) * LN2;

    const float s  = x0 + x1 + x2 + x3 + x4 + x5 + x6;
    const float d0 = fmaf(0.05f, s, fmaf(-0.03f, x1, fmaf(-0.02f, x2, 0.35f * (x3 + x5))));
    const float d1 = fmaf(0.05f, s, fmaf( 0.25f, x4, 0.40f * x6));
    const float d2 = fmaf(0.15f, s, fmaf(-0.05f, x0, fmaf(0.05f, x2,
                     fmaf(-0.13f, x3, fmaf(0.2f, x4, -0.12f * x5)))));
    const float d3 = s * 0.14285715f;

    const float d = (idx == 0) ? d0 : (idx == 1) ? d1 : (idx == 2) ? d2 : d3;
    const float c = (idx == 0) ? C0 : (idx == 1) ? C1 : (idx == 2) ? C2 : C3;
    return c + lse - d;
}

__global__ void __launch_bounds__(TPB, 7)
k_fused(const float* __restrict__ em, const int* __restrict__ tg,
        float* __restrict__ out, int n, int nchunks)
{
    __shared__ float s_x[NWARP][2][BUF_F];   // per-warp private double buffer (logits only)
    __shared__ float s_part[NWARP];
    __shared__ bool  s_last;

    const int wid  = threadIdx.x >> 5;
    const int lane = threadIdx.x & 31;
    const int gw   = blockIdx.x * NWARP + wid;   // global warp id
    const int nw   = gridDim.x * NWARP;          // total warps

    const uint32_t sb = (uint32_t)__cvta_generic_to_shared(&s_x[wid][0][0]);

    float acc = 0.f;
    int c = gw, buf = 0;

    // ---- prologue: prefetch first chunk (logits via cp.async, targets via regs) ----
    int tvc0 = 3, tvc1 = 3;
    if (c < nchunks) {
        const char* src = (const char*)(em + (size_t)c * BUF_F);
        CP16(sb + lane * 16,        src + lane * 16);
        CP16(sb + (lane + 32) * 16, src + (lane + 32) * 16);
        CP16(sb + (lane + 64) * 16, src + (lane + 64) * 16);
        if (lane < V4 - 96)
            CP16(sb + (lane + 96) * 16, src + (lane + 96) * 16);
        tvc0 = __ldg(tg + c * CHUNK + lane);
        tvc1 = __ldg(tg + c * CHUNK + lane + 32);
    }
    CP_COMMIT();

    // ---- warp-private pipelined loop: no block barriers ----
    for (; c < nchunks; c += nw) {
        const int cn = c + nw;
        int tvn0 = 3, tvn1 = 3;
        if (cn < nchunks) {
            const uint32_t db = sb + (buf ^ 1) * BUF_B;
            const char* src = (const char*)(em + (size_t)cn * BUF_F);
            CP16(db + lane * 16,        src + lane * 16);
            CP16(db + (lane + 32) * 16, src + (lane + 32) * 16);
            CP16(db + (lane + 64) * 16, src + (lane + 64) * 16);
            if (lane < V4 - 96)
                CP16(db + (lane + 96) * 16, src + (lane + 96) * 16);
            // register-pipelined target prefetch: consumed NEXT iteration -> latency hidden
            tvn0 = __ldg(tg + cn * CHUNK + lane);
            tvn1 = __ldg(tg + cn * CHUNK + lane + 32);
        }
        CP_COMMIT();          // possibly-empty group keeps wait-count uniform
        CP_WAIT1();           // current buf's copies done
        __syncwarp();         // ... across all lanes

        const float* xb = &s_x[wid][buf][0];
        acc += row_kl(xb + lane * 7,        tvc0);   // stride-7 rows: conflict-free
        acc += row_kl(xb + (lane + 32) * 7, tvc1);

        __syncwarp();         // all lanes consumed buf before it refills next iter
        buf ^= 1;
        tvc0 = tvn0;
        tvc1 = tvn1;
    }

    // ---- tail rows (none when n % 64 == 0): direct global, block 0 ----
    if (blockIdx.x == 0) {
        for (int row = nchunks * CHUNK + threadIdx.x; row < n; row += TPB)
            acc += row_kl(em + (size_t)row * 7, tg[row]);
    }

    // ---- block reduction ----
    #pragma unroll
    for (int o = 16; o > 0; o >>= 1)
        acc += __shfl_xor_sync(0xFFFFFFFFu, acc, o);
    if (lane == 0) s_part[wid] = acc;
    __syncthreads();

    if (threadIdx.x < 32) {
        float v = (lane < NWARP) ? s_part[lane] : 0.f;
        #pragma unroll
        for (int o = 4; o > 0; o >>= 1)
            v += __shfl_xor_sync(0xFFFFFFFFu, v, o);
        if (lane == 0)
            atomicAdd(&g_accum, (double)v);
    }

    // ---- last-block finalize (self-resetting for graph replay determinism) ----
    if (threadIdx.x == 0) {
        __threadfence();
        unsigned t = atomicAdd(&g_count, 1u);
        s_last = (t == gridDim.x - 1);
    }
    __syncthreads();
    if (s_last && threadIdx.x == 0) {
        out[0]  = (float)(g_accum / (double)n);
        g_accum = 0.0;
        g_count = 0u;
    }
}

extern "C" void kernel_launch(void* const* d_in, const int* in_sizes, int n_in,
                              void* d_out, int out_size)
{
    // metadata order: [0] fatigue_logits (unused), [1] emotion_logits, [2] fatigue_targets
    const float* em = (const float*)d_in[1];
    const int*   tg = (const int*)d_in[2];
    const int n = in_sizes[2];

    const int nchunks = n / CHUNK;
    int grid = 148 * 7;   // persistent, one wave (28.7 KB smem/block -> 7 blocks/SM)
    const int needed = (nchunks + NWARP - 1) / NWARP;
    if (needed >= 1 && grid > needed) grid = needed;
    if (grid < 1) grid = 1;

    k_fused<<<grid, TPB>>>(em, tg, (float*)d_out, n, nchunks);
}